// round 9
// baseline (speedup 1.0000x reference)
#include <cuda_runtime.h>
#include <math.h>

#define BATCH  4
#define SEQ    2048
#define DMODEL 1024
#define NHEAD  16
#define DHEAD  64
#define NBH    (BATCH * NHEAD)          // 64
#define MROWS  (BATCH * SEQ)            // 8192

// ---------------- scratch (no allocations allowed) ----------------
__device__ float g_q[(size_t)NBH * SEQ * DHEAD];     // 33.5 MB each
__device__ float g_k[(size_t)NBH * SEQ * DHEAD];
__device__ float g_v[(size_t)NBH * SEQ * DHEAD];
__device__ float g_ctx[(size_t)MROWS * DMODEL];

// =====================================================================
// Tiled fp32 SGEMM:  out = (X[M,1024] @ W[1024,1024] + bias) * scale
// head_split=1 -> write in [b,h,s,d] ( (b*H+h)*S + s )*DH + d layout
// head_split=0 -> plain row-major [M, D]
// Block tile 128x128, K-step 8, 256 threads, 8x8 microtile.
// =====================================================================
__global__ __launch_bounds__(256) void proj_kernel(
    const float* __restrict__ X, const float* __restrict__ W,
    const float* __restrict__ bias, float* __restrict__ out,
    float scale, int head_split)
{
    __shared__ float As[8][128];   // transposed A tile
    __shared__ float Bs[8][128];

    const int tid = threadIdx.x;
    const int tx  = tid & 15;
    const int ty  = tid >> 4;
    const int row0 = blockIdx.x * 128;
    const int col0 = blockIdx.y * 128;

    float acc[8][8];
#pragma unroll
    for (int i = 0; i < 8; i++)
#pragma unroll
        for (int j = 0; j < 8; j++) acc[i][j] = 0.0f;

    const int a_row = tid >> 1;          // 0..127
    const int a_col = (tid & 1) * 4;     // 0 or 4
    const int b_row = tid >> 5;          // 0..7
    const int b_col = (tid & 31) * 4;    // 0..124

    const float* Ap = X + (size_t)(row0 + a_row) * DMODEL + a_col;
    const float* Bp = W + (size_t)b_row * DMODEL + col0 + b_col;

    for (int kt = 0; kt < DMODEL; kt += 8) {
        float4 av = *(const float4*)(Ap + kt);
        float4 bv = *(const float4*)(Bp + (size_t)kt * DMODEL);
        As[a_col + 0][a_row] = av.x;
        As[a_col + 1][a_row] = av.y;
        As[a_col + 2][a_row] = av.z;
        As[a_col + 3][a_row] = av.w;
        *(float4*)&Bs[b_row][b_col] = bv;
        __syncthreads();

#pragma unroll
        for (int kk = 0; kk < 8; kk++) {
            float a[8], b[8];
            *(float4*)&a[0] = *(const float4*)&As[kk][ty * 4];
            *(float4*)&a[4] = *(const float4*)&As[kk][64 + ty * 4];
            *(float4*)&b[0] = *(const float4*)&Bs[kk][tx * 4];
            *(float4*)&b[4] = *(const float4*)&Bs[kk][64 + tx * 4];
#pragma unroll
            for (int i = 0; i < 8; i++)
#pragma unroll
                for (int j = 0; j < 8; j++)
                    acc[i][j] = fmaf(a[i], b[j], acc[i][j]);
        }
        __syncthreads();
    }

#pragma unroll
    for (int i = 0; i < 8; i++) {
        int r  = row0 + ((i < 4) ? (ty * 4 + i) : (64 + ty * 4 + i - 4));
        int bb = r >> 11;                // /SEQ
        int ss = r & (SEQ - 1);
#pragma unroll
        for (int jg = 0; jg < 2; jg++) {
            int c = col0 + jg * 64 + tx * 4;
            float4 b4 = *(const float4*)&bias[c];
            float4 v;
            v.x = (acc[i][jg * 4 + 0] + b4.x) * scale;
            v.y = (acc[i][jg * 4 + 1] + b4.y) * scale;
            v.z = (acc[i][jg * 4 + 2] + b4.z) * scale;
            v.w = (acc[i][jg * 4 + 3] + b4.w) * scale;
            if (head_split) {
                int hh = c >> 6;
                int dd = c & 63;
                *(float4*)&out[((size_t)(bb * NHEAD + hh) * SEQ + ss) * DHEAD + dd] = v;
            } else {
                *(float4*)&out[(size_t)r * DMODEL + c] = v;
            }
        }
    }
}

// =====================================================================
// Flash attention, fp32.  grid = (S/128, BH), block 256.
// Per block: 128 queries x full key range, online softmax.
// When h==0 also dumps RAW scores into top_attn (softmaxed later).
// =====================================================================
#define QSTRIDE 68
#define PSTRIDE 132
#define FLASH_SMEM ((3 * 128 * QSTRIDE + 128 * PSTRIDE) * 4)   // 172032 B

__global__ __launch_bounds__(256, 1) void flash_kernel(float* __restrict__ topattn)
{
    extern __shared__ float smem[];
    float* Qs = smem;
    float* Ks = smem + 128 * QSTRIDE;
    float* Vs = smem + 2 * 128 * QSTRIDE;
    float* Ps = smem + 3 * 128 * QSTRIDE;

    const int tid = threadIdx.x;
    const int tx  = tid & 15;
    const int ty  = tid >> 4;
    const int bh  = blockIdx.y;
    const int q0  = blockIdx.x * 128;
    const int b   = bh >> 4;
    const int h   = bh & 15;

    const float* Qg = g_q + (size_t)bh * SEQ * DHEAD + (size_t)q0 * DHEAD;
    const float* Kg = g_k + (size_t)bh * SEQ * DHEAD;
    const float* Vg = g_v + (size_t)bh * SEQ * DHEAD;

    // load Q tile (128 x 64) into smem
#pragma unroll
    for (int t = 0; t < 8; t++) {
        int idx = tid + t * 256;
        int row = idx >> 4;
        int c4  = (idx & 15) << 2;
        *(float4*)&Qs[row * QSTRIDE + c4] = *(const float4*)(Qg + row * DHEAD + c4);
    }

    int rloc[8];
#pragma unroll
    for (int i = 0; i < 8; i++)
        rloc[i] = (i < 4) ? (ty * 4 + i) : (64 + ty * 4 + i - 4);

    float mrow[8], lrow[8], ctx[8][4];
#pragma unroll
    for (int i = 0; i < 8; i++) {
        mrow[i] = -3.0e38f;
        lrow[i] = 0.0f;
#pragma unroll
        for (int j = 0; j < 4; j++) ctx[i][j] = 0.0f;
    }

    for (int kt = 0; kt < SEQ / 128; kt++) {
        const int k0 = kt * 128;
        __syncthreads();   // previous iter's PV done with Ps/Vs
#pragma unroll
        for (int t = 0; t < 8; t++) {
            int idx = tid + t * 256;
            int row = idx >> 4;
            int c4  = (idx & 15) << 2;
            *(float4*)&Ks[row * QSTRIDE + c4] = *(const float4*)(Kg + (k0 + row) * DHEAD + c4);
            *(float4*)&Vs[row * QSTRIDE + c4] = *(const float4*)(Vg + (k0 + row) * DHEAD + c4);
        }
        __syncthreads();

        // ---- S = Q @ K^T (128x128 tile in regs, 8x8 per thread) ----
        float s[8][8];
#pragma unroll
        for (int i = 0; i < 8; i++)
#pragma unroll
            for (int j = 0; j < 8; j++) s[i][j] = 0.0f;

#pragma unroll 2
        for (int d = 0; d < DHEAD; d += 4) {
            float4 a4[8], b4[8];
#pragma unroll
            for (int i = 0; i < 8; i++)
                a4[i] = *(const float4*)&Qs[rloc[i] * QSTRIDE + d];
#pragma unroll
            for (int j = 0; j < 8; j++) {
                int col = (j < 4) ? (tx * 4 + j) : (64 + tx * 4 + j - 4);
                b4[j] = *(const float4*)&Ks[col * QSTRIDE + d];
            }
#pragma unroll
            for (int i = 0; i < 8; i++)
#pragma unroll
                for (int j = 0; j < 8; j++) {
                    s[i][j] = fmaf(a4[i].x, b4[j].x, s[i][j]);
                    s[i][j] = fmaf(a4[i].y, b4[j].y, s[i][j]);
                    s[i][j] = fmaf(a4[i].z, b4[j].z, s[i][j]);
                    s[i][j] = fmaf(a4[i].w, b4[j].w, s[i][j]);
                }
        }

        // ---- head-0: dump raw scores into top_attn output region ----
        if (h == 0) {
            float* op = topattn + ((size_t)b * SEQ + q0) * SEQ + k0;
#pragma unroll
            for (int i = 0; i < 8; i++) {
                float* rp = op + (size_t)rloc[i] * SEQ;
                *(float4*)&rp[tx * 4]      = make_float4(s[i][0], s[i][1], s[i][2], s[i][3]);
                *(float4*)&rp[64 + tx * 4] = make_float4(s[i][4], s[i][5], s[i][6], s[i][7]);
            }
        }

        // ---- online softmax (rows span 16 consecutive lanes) ----
#pragma unroll
        for (int i = 0; i < 8; i++) {
            float mx = s[i][0];
#pragma unroll
            for (int j = 1; j < 8; j++) mx = fmaxf(mx, s[i][j]);
#pragma unroll
            for (int o = 8; o >= 1; o >>= 1)
                mx = fmaxf(mx, __shfl_xor_sync(0xffffffffu, mx, o, 16));
            float mn    = fmaxf(mrow[i], mx);
            float alpha = __expf(mrow[i] - mn);
            mrow[i] = mn;
            lrow[i] *= alpha;
#pragma unroll
            for (int j = 0; j < 4; j++) ctx[i][j] *= alpha;
            float rs = 0.0f;
#pragma unroll
            for (int j = 0; j < 8; j++) {
                float p = __expf(s[i][j] - mn);
                s[i][j] = p;
                rs += p;
            }
#pragma unroll
            for (int o = 8; o >= 1; o >>= 1)
                rs += __shfl_xor_sync(0xffffffffu, rs, o, 16);
            lrow[i] += rs;
        }

        // ---- stage P through smem, then PV ----
#pragma unroll
        for (int i = 0; i < 8; i++) {
            float* pp = &Ps[rloc[i] * PSTRIDE];
            *(float4*)&pp[tx * 4]      = make_float4(s[i][0], s[i][1], s[i][2], s[i][3]);
            *(float4*)&pp[64 + tx * 4] = make_float4(s[i][4], s[i][5], s[i][6], s[i][7]);
        }
        __syncthreads();

#pragma unroll 2
        for (int kc = 0; kc < 128; kc += 4) {
            float4 v4[4];
#pragma unroll
            for (int kk = 0; kk < 4; kk++)
                v4[kk] = *(const float4*)&Vs[(kc + kk) * QSTRIDE + tx * 4];
#pragma unroll
            for (int i = 0; i < 8; i++) {
                float4 p4 = *(const float4*)&Ps[rloc[i] * PSTRIDE + kc];
                ctx[i][0] = fmaf(p4.x, v4[0].x, ctx[i][0]);
                ctx[i][0] = fmaf(p4.y, v4[1].x, ctx[i][0]);
                ctx[i][0] = fmaf(p4.z, v4[2].x, ctx[i][0]);
                ctx[i][0] = fmaf(p4.w, v4[3].x, ctx[i][0]);
                ctx[i][1] = fmaf(p4.x, v4[0].y, ctx[i][1]);
                ctx[i][1] = fmaf(p4.y, v4[1].y, ctx[i][1]);
                ctx[i][1] = fmaf(p4.z, v4[2].y, ctx[i][1]);
                ctx[i][1] = fmaf(p4.w, v4[3].y, ctx[i][1]);
                ctx[i][2] = fmaf(p4.x, v4[0].z, ctx[i][2]);
                ctx[i][2] = fmaf(p4.y, v4[1].z, ctx[i][2]);
                ctx[i][2] = fmaf(p4.z, v4[2].z, ctx[i][2]);
                ctx[i][2] = fmaf(p4.w, v4[3].z, ctx[i][2]);
                ctx[i][3] = fmaf(p4.x, v4[0].w, ctx[i][3]);
                ctx[i][3] = fmaf(p4.y, v4[1].w, ctx[i][3]);
                ctx[i][3] = fmaf(p4.z, v4[2].w, ctx[i][3]);
                ctx[i][3] = fmaf(p4.w, v4[3].w, ctx[i][3]);
            }
        }
    }

    // ---- normalize + write ctx in [B,S, h*DH+d] layout ----
#pragma unroll
    for (int i = 0; i < 8; i++) {
        float inv = 1.0f / lrow[i];
        int   r   = q0 + rloc[i];
        size_t idx = ((size_t)b * SEQ + r) * DMODEL + h * DHEAD + tx * 4;
        *(float4*)&g_ctx[idx] =
            make_float4(ctx[i][0] * inv, ctx[i][1] * inv, ctx[i][2] * inv, ctx[i][3] * inv);
    }
}

// =====================================================================
// In-place row softmax over top_attn (rows of 2048). grid = B*S.
// =====================================================================
__global__ __launch_bounds__(256) void softmax_rows_kernel(float* __restrict__ data)
{
    __shared__ float red[8];
    float* p = data + (size_t)blockIdx.x * SEQ;
    const int t = threadIdx.x;

    float4 v0 = ((const float4*)p)[t];
    float4 v1 = ((const float4*)p)[t + 256];

    float mx = fmaxf(fmaxf(fmaxf(v0.x, v0.y), fmaxf(v0.z, v0.w)),
                     fmaxf(fmaxf(v1.x, v1.y), fmaxf(v1.z, v1.w)));
#pragma unroll
    for (int o = 16; o >= 1; o >>= 1)
        mx = fmaxf(mx, __shfl_xor_sync(0xffffffffu, mx, o));
    if ((t & 31) == 0) red[t >> 5] = mx;
    __syncthreads();
    float m = red[0];
#pragma unroll
    for (int i = 1; i < 8; i++) m = fmaxf(m, red[i]);
    __syncthreads();

    v0.x = __expf(v0.x - m); v0.y = __expf(v0.y - m);
    v0.z = __expf(v0.z - m); v0.w = __expf(v0.w - m);
    v1.x = __expf(v1.x - m); v1.y = __expf(v1.y - m);
    v1.z = __expf(v1.z - m); v1.w = __expf(v1.w - m);

    float sm = v0.x + v0.y + v0.z + v0.w + v1.x + v1.y + v1.z + v1.w;
#pragma unroll
    for (int o = 16; o >= 1; o >>= 1)
        sm += __shfl_xor_sync(0xffffffffu, sm, o);
    if ((t & 31) == 0) red[t >> 5] = sm;
    __syncthreads();
    float tot = 0.0f;
#pragma unroll
    for (int i = 0; i < 8; i++) tot += red[i];
    float inv = 1.0f / tot;

    v0.x *= inv; v0.y *= inv; v0.z *= inv; v0.w *= inv;
    v1.x *= inv; v1.y *= inv; v1.z *= inv; v1.w *= inv;
    ((float4*)p)[t]       = v0;
    ((float4*)p)[t + 256] = v1;
}

// =====================================================================
// kernel_launch: 6 launches, graph-capturable, no allocations.
// Input order (metadata): key, value, query, Wk, bk, Wv, bv, Wq, bq, Wo, bo
// Output: [output (4,2048,1024) | top_attn (4,2048,2048)]
// =====================================================================
extern "C" void kernel_launch(void* const* d_in, const int* in_sizes, int n_in,
                              void* d_out, int out_size)
{
    (void)in_sizes; (void)n_in; (void)out_size;
    const float* key_in   = (const float*)d_in[0];
    const float* value_in = (const float*)d_in[1];
    const float* query_in = (const float*)d_in[2];
    const float* Wk = (const float*)d_in[3];
    const float* bk = (const float*)d_in[4];
    const float* Wv = (const float*)d_in[5];
    const float* bv = (const float*)d_in[6];
    const float* Wq = (const float*)d_in[7];
    const float* bq = (const float*)d_in[8];
    const float* Wo = (const float*)d_in[9];
    const float* bo = (const float*)d_in[10];

    float* out     = (float*)d_out;
    float* topattn = out + (size_t)MROWS * DMODEL;

    void *pq, *pk, *pv, *pctx;
    cudaGetSymbolAddress(&pq, g_q);
    cudaGetSymbolAddress(&pk, g_k);
    cudaGetSymbolAddress(&pv, g_v);
    cudaGetSymbolAddress(&pctx, g_ctx);

    dim3 pgrid(MROWS / 128, DMODEL / 128);
    // Q projection includes the 1/sqrt(DH) = 0.125 scale
    proj_kernel<<<pgrid, 256>>>(query_in, Wq, bq, (float*)pq, 0.125f, 1);
    proj_kernel<<<pgrid, 256>>>(key_in,   Wk, bk, (float*)pk, 1.0f,   1);
    proj_kernel<<<pgrid, 256>>>(value_in, Wv, bv, (float*)pv, 1.0f,   1);

    cudaFuncSetAttribute(flash_kernel,
                         cudaFuncAttributeMaxDynamicSharedMemorySize, FLASH_SMEM);
    flash_kernel<<<dim3(SEQ / 128, NBH), 256, FLASH_SMEM>>>(topattn);

    softmax_rows_kernel<<<BATCH * SEQ, 256>>>(topattn);

    proj_kernel<<<pgrid, 256>>>((const float*)pctx, Wo, bo, out, 1.0f, 0);
}

// round 16
// speedup vs baseline: 1.3130x; 1.3130x over previous
#include <cuda_runtime.h>
#include <cuda_bf16.h>
#include <math.h>
#include <stdint.h>

#define BATCH  4
#define SEQ    2048
#define DMODEL 1024
#define NHEAD  16
#define DHEAD  64
#define NBH    (BATCH * NHEAD)          // 64
#define MROWS  (BATCH * SEQ)            // 8192
#define KSPLIT 3072                     // 3 * DMODEL (bf16-split interleave)

// ---------------- scratch (no allocations allowed) ----------------
__device__ float g_q[(size_t)NBH * SEQ * DHEAD];
__device__ float g_k[(size_t)NBH * SEQ * DHEAD];
__device__ float g_v[(size_t)NBH * SEQ * DHEAD];
__device__ float g_ctx[(size_t)MROWS * DMODEL];
__device__ __nv_bfloat16 g_asplit[(size_t)MROWS * KSPLIT];   // 48 MB
__device__ __nv_bfloat16 g_bsplit[(size_t)DMODEL * KSPLIT];  // 6 MB

// =====================================================================
// Portable PTX helpers (sm_80+ features only — NO tcgen05 on this toolchain)
// =====================================================================
__device__ __forceinline__ uint32_t smem_u32(const void* p) {
    return (uint32_t)__cvta_generic_to_shared(p);
}
__device__ __forceinline__ void cp16(uint32_t dst, const void* src) {
    asm volatile("cp.async.cg.shared.global [%0], [%1], 16;" :: "r"(dst), "l"(src));
}
#define CP_COMMIT() asm volatile("cp.async.commit_group;" ::: "memory")
#define CP_WAIT1()  asm volatile("cp.async.wait_group 1;" ::: "memory")
#define CP_WAIT0()  asm volatile("cp.async.wait_group 0;" ::: "memory")

__device__ __forceinline__ void ldsm4(uint32_t* r, uint32_t addr) {
    asm volatile("ldmatrix.sync.aligned.m8n8.x4.shared.b16 {%0,%1,%2,%3}, [%4];"
                 : "=r"(r[0]), "=r"(r[1]), "=r"(r[2]), "=r"(r[3]) : "r"(addr));
}
__device__ __forceinline__ void mma16816(float* c, const uint32_t* a, const uint32_t* b) {
    asm volatile(
        "mma.sync.aligned.m16n8k16.row.col.f32.bf16.bf16.f32 "
        "{%0,%1,%2,%3}, {%4,%5,%6,%7}, {%8,%9}, {%0,%1,%2,%3};"
        : "+f"(c[0]), "+f"(c[1]), "+f"(c[2]), "+f"(c[3])
        : "r"(a[0]), "r"(a[1]), "r"(a[2]), "r"(a[3]), "r"(b[0]), "r"(b[1]));
}

// =====================================================================
// Split kernels: fp32 -> bf16 (hi,lo) in K-interleaved layout
// A:  [hi | hi | lo]      B(transposed): [hi | lo | hi]
// =====================================================================
__global__ __launch_bounds__(256) void split_a_kernel(
    const float* __restrict__ X, __nv_bfloat16* __restrict__ out)
{
    int gid = blockIdx.x * 256 + threadIdx.x;     // one float4 per thread
    float4 x = *(const float4*)(X + (size_t)gid * 4);
    int r = gid >> 8;                             // 256 float4 per row of 1024
    int c = (gid & 255) * 4;

    __nv_bfloat16 h0 = __float2bfloat16(x.x), h1 = __float2bfloat16(x.y);
    __nv_bfloat16 h2 = __float2bfloat16(x.z), h3 = __float2bfloat16(x.w);
    __nv_bfloat16 l0 = __float2bfloat16(x.x - __bfloat162float(h0));
    __nv_bfloat16 l1 = __float2bfloat16(x.y - __bfloat162float(h1));
    __nv_bfloat16 l2 = __float2bfloat16(x.z - __bfloat162float(h2));
    __nv_bfloat16 l3 = __float2bfloat16(x.w - __bfloat162float(h3));

    __nv_bfloat16 hi[4] = {h0, h1, h2, h3};
    __nv_bfloat16 lo[4] = {l0, l1, l2, l3};
    __nv_bfloat16* rp = out + (size_t)r * KSPLIT;
    *(uint2*)&rp[c]        = *(uint2*)hi;
    *(uint2*)&rp[1024 + c] = *(uint2*)hi;
    *(uint2*)&rp[2048 + c] = *(uint2*)lo;
}

// W[k][n] -> out[n][k'] : transpose + split. grid (32, 32), block (32, 8)
__global__ void split_b_kernel(const float* __restrict__ W,
                               __nv_bfloat16* __restrict__ out)
{
    __shared__ float tile[32][33];
    int n0 = blockIdx.x * 32, k0 = blockIdx.y * 32;
    int tx = threadIdx.x, ty = threadIdx.y;
#pragma unroll
    for (int i = 0; i < 32; i += 8)
        tile[ty + i][tx] = W[(size_t)(k0 + ty + i) * DMODEL + n0 + tx];
    __syncthreads();
#pragma unroll
    for (int i = 0; i < 32; i += 8) {
        int n = n0 + ty + i, k = k0 + tx;
        float x = tile[tx][ty + i];
        __nv_bfloat16 hi = __float2bfloat16(x);
        __nv_bfloat16 lo = __float2bfloat16(x - __bfloat162float(hi));
        __nv_bfloat16* rp = out + (size_t)n * KSPLIT;
        rp[k]        = hi;
        rp[1024 + k] = lo;
        rp[2048 + k] = hi;
    }
}

// =====================================================================
// mma.sync bf16 GEMM: C[8192,1024] = Asplit[8192,3072] @ Bsplit[1024,3072]^T
// CTA 128x128, 8 warps (2M x 4N), warp tile 64x32, K-stage 64, cp.async
// double buffer. smem rows padded to 144B (9 chunks) -> conflict-free ldmatrix.
// grid (N/128 = 8, M/128 = 64)  (x-fast -> A tile reused via L2)
// =====================================================================
#define BK        64
#define ROWB      144                     // padded row stride in bytes
#define TILEB     (128 * ROWB)            // 18432 B per matrix per stage
#define GEMM_SMEM (4 * TILEB)             // 73728 B  (A0 B0 A1 B1)
#define NSTAGE    (KSPLIT / BK)           // 48

__device__ __forceinline__ void gemm_load_stage(
    uint32_t sa, uint32_t sb, const __nv_bfloat16* __restrict__ A,
    const __nv_bfloat16* __restrict__ B, int row0, int col0, int k0, int tid)
{
#pragma unroll
    for (int t = 0; t < 8; t++) {
        int idx = tid + t * 256;              // 0..2047
        int row = (idx >> 3) & 127;
        int c   = idx & 7;                    // 16B chunk
        const __nv_bfloat16* src = (idx < 1024)
            ? A + (size_t)(row0 + row) * KSPLIT + k0 + c * 8
            : B + (size_t)(col0 + row) * KSPLIT + k0 + c * 8;
        uint32_t dst = ((idx < 1024) ? sa : sb) + row * ROWB + c * 16;
        cp16(dst, src);
    }
}

__global__ __launch_bounds__(256) void gemm_mma_kernel(
    const __nv_bfloat16* __restrict__ A, const __nv_bfloat16* __restrict__ B,
    const float* __restrict__ bias, float* __restrict__ out,
    float scale, int head_split)
{
    extern __shared__ char smem[];
    const uint32_t sb0 = smem_u32(smem);
    const int tid  = threadIdx.x;
    const int wid  = tid >> 5;
    const int lane = tid & 31;
    const int wy   = wid >> 2;            // 0..1  (M)
    const int wx   = wid & 3;             // 0..3  (N)
    const int col0 = blockIdx.x * 128;
    const int row0 = blockIdx.y * 128;

    // stage smem bases: A0 B0 A1 B1
    const uint32_t sa[2] = {sb0,             sb0 + 2 * TILEB};
    const uint32_t sbv[2] = {sb0 + TILEB,    sb0 + 3 * TILEB};

    // per-thread ldmatrix base addresses (within a stage buffer)
    // A: lanes 0-15 -> rows (wy*64 + lane), chunk 0 ; lanes 16-31 -> same rows, chunk 1
    const uint32_t a_off = (uint32_t)((wy * 64 + (lane & 15)) * ROWB + (lane >> 4) * 16);
    // B: rows = wx*32 + ((lane>>4)&1)*8 + (lane&7), chunk = (lane>>3)&1
    const uint32_t b_off = (uint32_t)((wx * 32 + ((lane >> 4) & 1) * 8 + (lane & 7)) * ROWB
                                      + ((lane >> 3) & 1) * 16);

    float acc[4][4][4];
#pragma unroll
    for (int i = 0; i < 4; i++)
#pragma unroll
        for (int j = 0; j < 4; j++)
#pragma unroll
            for (int e = 0; e < 4; e++) acc[i][j][e] = 0.0f;

    gemm_load_stage(sa[0], sbv[0], A, B, row0, col0, 0, tid);
    CP_COMMIT();

    for (int s = 0; s < NSTAGE; s++) {
        const int buf = s & 1;
        if (s + 1 < NSTAGE) {
            gemm_load_stage(sa[buf ^ 1], sbv[buf ^ 1], A, B, row0, col0,
                            (s + 1) * BK, tid);
            CP_COMMIT();
            CP_WAIT1();
        } else {
            CP_WAIT0();
        }
        __syncthreads();

        const uint32_t abase = sa[buf] + a_off;
        const uint32_t bbase = sbv[buf] + b_off;
#pragma unroll
        for (int kk = 0; kk < BK / 16; kk++) {
            uint32_t af[4][4], bf[8];
#pragma unroll
            for (int i = 0; i < 4; i++)
                ldsm4(af[i], abase + i * 16 * ROWB + kk * 32);
#pragma unroll
            for (int j2 = 0; j2 < 2; j2++)
                ldsm4(&bf[j2 * 4], bbase + j2 * 16 * ROWB + kk * 32);
#pragma unroll
            for (int i = 0; i < 4; i++)
#pragma unroll
                for (int j = 0; j < 4; j++)
                    mma16816(acc[i][j], af[i], &bf[j * 2]);
        }
        __syncthreads();
    }

    // ---- epilogue: bias + scale + (optional) head-split store ----
#pragma unroll
    for (int i = 0; i < 4; i++) {
        const int r0t = row0 + wy * 64 + i * 16 + (lane >> 2);
#pragma unroll
        for (int j = 0; j < 4; j++) {
            const int cc = col0 + wx * 32 + j * 8 + (lane & 3) * 2;
            float2 bi = *(const float2*)&bias[cc];
            float2 v0, v1;
            v0.x = (acc[i][j][0] + bi.x) * scale;
            v0.y = (acc[i][j][1] + bi.y) * scale;
            v1.x = (acc[i][j][2] + bi.x) * scale;
            v1.y = (acc[i][j][3] + bi.y) * scale;
            if (head_split) {
                const int h = cc >> 6, d = cc & 63;
                int bb = r0t >> 11, ss = r0t & (SEQ - 1);
                *(float2*)&out[((size_t)(bb * NHEAD + h) * SEQ + ss) * DHEAD + d] = v0;
                int r1t = r0t + 8;
                bb = r1t >> 11; ss = r1t & (SEQ - 1);
                *(float2*)&out[((size_t)(bb * NHEAD + h) * SEQ + ss) * DHEAD + d] = v1;
            } else {
                *(float2*)&out[(size_t)r0t * DMODEL + cc]       = v0;
                *(float2*)&out[(size_t)(r0t + 8) * DMODEL + cc] = v1;
            }
        }
    }
}

// =====================================================================
// Flash attention, fp32 (unchanged).  grid = (S/128, BH), block 256.
// =====================================================================
#define QSTRIDE 68
#define PSTRIDE 132
#define FLASH_SMEM ((3 * 128 * QSTRIDE + 128 * PSTRIDE) * 4)   // 172032 B

__global__ __launch_bounds__(256, 1) void flash_kernel(float* __restrict__ topattn)
{
    extern __shared__ float fsm[];
    float* Qs = fsm;
    float* Ks = fsm + 128 * QSTRIDE;
    float* Vs = fsm + 2 * 128 * QSTRIDE;
    float* Ps = fsm + 3 * 128 * QSTRIDE;

    const int tid = threadIdx.x;
    const int tx  = tid & 15;
    const int ty  = tid >> 4;
    const int bh  = blockIdx.y;
    const int q0  = blockIdx.x * 128;
    const int b   = bh >> 4;
    const int h   = bh & 15;

    const float* Qg = g_q + (size_t)bh * SEQ * DHEAD + (size_t)q0 * DHEAD;
    const float* Kg = g_k + (size_t)bh * SEQ * DHEAD;
    const float* Vg = g_v + (size_t)bh * SEQ * DHEAD;

#pragma unroll
    for (int t = 0; t < 8; t++) {
        int idx = tid + t * 256;
        int row = idx >> 4;
        int c4  = (idx & 15) << 2;
        *(float4*)&Qs[row * QSTRIDE + c4] = *(const float4*)(Qg + row * DHEAD + c4);
    }

    int rloc[8];
#pragma unroll
    for (int i = 0; i < 8; i++)
        rloc[i] = (i < 4) ? (ty * 4 + i) : (64 + ty * 4 + i - 4);

    float mrow[8], lrow[8], ctx[8][4];
#pragma unroll
    for (int i = 0; i < 8; i++) {
        mrow[i] = -3.0e38f;
        lrow[i] = 0.0f;
#pragma unroll
        for (int j = 0; j < 4; j++) ctx[i][j] = 0.0f;
    }

    for (int kt = 0; kt < SEQ / 128; kt++) {
        const int k0 = kt * 128;
        __syncthreads();
#pragma unroll
        for (int t = 0; t < 8; t++) {
            int idx = tid + t * 256;
            int row = idx >> 4;
            int c4  = (idx & 15) << 2;
            *(float4*)&Ks[row * QSTRIDE + c4] = *(const float4*)(Kg + (k0 + row) * DHEAD + c4);
            *(float4*)&Vs[row * QSTRIDE + c4] = *(const float4*)(Vg + (k0 + row) * DHEAD + c4);
        }
        __syncthreads();

        float s[8][8];
#pragma unroll
        for (int i = 0; i < 8; i++)
#pragma unroll
            for (int j = 0; j < 8; j++) s[i][j] = 0.0f;

#pragma unroll 2
        for (int d = 0; d < DHEAD; d += 4) {
            float4 a4[8], b4[8];
#pragma unroll
            for (int i = 0; i < 8; i++)
                a4[i] = *(const float4*)&Qs[rloc[i] * QSTRIDE + d];
#pragma unroll
            for (int j = 0; j < 8; j++) {
                int col = (j < 4) ? (tx * 4 + j) : (64 + tx * 4 + j - 4);
                b4[j] = *(const float4*)&Ks[col * QSTRIDE + d];
            }
#pragma unroll
            for (int i = 0; i < 8; i++)
#pragma unroll
                for (int j = 0; j < 8; j++) {
                    s[i][j] = fmaf(a4[i].x, b4[j].x, s[i][j]);
                    s[i][j] = fmaf(a4[i].y, b4[j].y, s[i][j]);
                    s[i][j] = fmaf(a4[i].z, b4[j].z, s[i][j]);
                    s[i][j] = fmaf(a4[i].w, b4[j].w, s[i][j]);
                }
        }

        if (h == 0) {
            float* op = topattn + ((size_t)b * SEQ + q0) * SEQ + k0;
#pragma unroll
            for (int i = 0; i < 8; i++) {
                float* rp = op + (size_t)rloc[i] * SEQ;
                *(float4*)&rp[tx * 4]      = make_float4(s[i][0], s[i][1], s[i][2], s[i][3]);
                *(float4*)&rp[64 + tx * 4] = make_float4(s[i][4], s[i][5], s[i][6], s[i][7]);
            }
        }

#pragma unroll
        for (int i = 0; i < 8; i++) {
            float mx = s[i][0];
#pragma unroll
            for (int j = 1; j < 8; j++) mx = fmaxf(mx, s[i][j]);
#pragma unroll
            for (int o = 8; o >= 1; o >>= 1)
                mx = fmaxf(mx, __shfl_xor_sync(0xffffffffu, mx, o, 16));
            float mn    = fmaxf(mrow[i], mx);
            float alpha = __expf(mrow[i] - mn);
            mrow[i] = mn;
            lrow[i] *= alpha;
#pragma unroll
            for (int j = 0; j < 4; j++) ctx[i][j] *= alpha;
            float rs = 0.0f;
#pragma unroll
            for (int j = 0; j < 8; j++) {
                float p = __expf(s[i][j] - mn);
                s[i][j] = p;
                rs += p;
            }
#pragma unroll
            for (int o = 8; o >= 1; o >>= 1)
                rs += __shfl_xor_sync(0xffffffffu, rs, o, 16);
            lrow[i] += rs;
        }

#pragma unroll
        for (int i = 0; i < 8; i++) {
            float* pp = &Ps[rloc[i] * PSTRIDE];
            *(float4*)&pp[tx * 4]      = make_float4(s[i][0], s[i][1], s[i][2], s[i][3]);
            *(float4*)&pp[64 + tx * 4] = make_float4(s[i][4], s[i][5], s[i][6], s[i][7]);
        }
        __syncthreads();

#pragma unroll 2
        for (int kc = 0; kc < 128; kc += 4) {
            float4 v4[4];
#pragma unroll
            for (int kk = 0; kk < 4; kk++)
                v4[kk] = *(const float4*)&Vs[(kc + kk) * QSTRIDE + tx * 4];
#pragma unroll
            for (int i = 0; i < 8; i++) {
                float4 p4 = *(const float4*)&Ps[rloc[i] * PSTRIDE + kc];
                ctx[i][0] = fmaf(p4.x, v4[0].x, ctx[i][0]);
                ctx[i][0] = fmaf(p4.y, v4[1].x, ctx[i][0]);
                ctx[i][0] = fmaf(p4.z, v4[2].x, ctx[i][0]);
                ctx[i][0] = fmaf(p4.w, v4[3].x, ctx[i][0]);
                ctx[i][1] = fmaf(p4.x, v4[0].y, ctx[i][1]);
                ctx[i][1] = fmaf(p4.y, v4[1].y, ctx[i][1]);
                ctx[i][1] = fmaf(p4.z, v4[2].y, ctx[i][1]);
                ctx[i][1] = fmaf(p4.w, v4[3].y, ctx[i][1]);
                ctx[i][2] = fmaf(p4.x, v4[0].z, ctx[i][2]);
                ctx[i][2] = fmaf(p4.y, v4[1].z, ctx[i][2]);
                ctx[i][2] = fmaf(p4.z, v4[2].z, ctx[i][2]);
                ctx[i][2] = fmaf(p4.w, v4[3].z, ctx[i][2]);
                ctx[i][3] = fmaf(p4.x, v4[0].w, ctx[i][3]);
                ctx[i][3] = fmaf(p4.y, v4[1].w, ctx[i][3]);
                ctx[i][3] = fmaf(p4.z, v4[2].w, ctx[i][3]);
                ctx[i][3] = fmaf(p4.w, v4[3].w, ctx[i][3]);
            }
        }
    }

#pragma unroll
    for (int i = 0; i < 8; i++) {
        float inv = 1.0f / lrow[i];
        int   r   = q0 + rloc[i];
        size_t idx = ((size_t)b * SEQ + r) * DMODEL + h * DHEAD + tx * 4;
        *(float4*)&g_ctx[idx] =
            make_float4(ctx[i][0] * inv, ctx[i][1] * inv, ctx[i][2] * inv, ctx[i][3] * inv);
    }
}

// =====================================================================
// In-place row softmax over top_attn (rows of 2048). grid = B*S.
// =====================================================================
__global__ __launch_bounds__(256) void softmax_rows_kernel(float* __restrict__ data)
{
    __shared__ float red[8];
    float* p = data + (size_t)blockIdx.x * SEQ;
    const int t = threadIdx.x;

    float4 v0 = ((const float4*)p)[t];
    float4 v1 = ((const float4*)p)[t + 256];

    float mx = fmaxf(fmaxf(fmaxf(v0.x, v0.y), fmaxf(v0.z, v0.w)),
                     fmaxf(fmaxf(v1.x, v1.y), fmaxf(v1.z, v1.w)));
#pragma unroll
    for (int o = 16; o >= 1; o >>= 1)
        mx = fmaxf(mx, __shfl_xor_sync(0xffffffffu, mx, o));
    if ((t & 31) == 0) red[t >> 5] = mx;
    __syncthreads();
    float m = red[0];
#pragma unroll
    for (int i = 1; i < 8; i++) m = fmaxf(m, red[i]);
    __syncthreads();

    v0.x = __expf(v0.x - m); v0.y = __expf(v0.y - m);
    v0.z = __expf(v0.z - m); v0.w = __expf(v0.w - m);
    v1.x = __expf(v1.x - m); v1.y = __expf(v1.y - m);
    v1.z = __expf(v1.z - m); v1.w = __expf(v1.w - m);

    float sm = v0.x + v0.y + v0.z + v0.w + v1.x + v1.y + v1.z + v1.w;
#pragma unroll
    for (int o = 16; o >= 1; o >>= 1)
        sm += __shfl_xor_sync(0xffffffffu, sm, o);
    if ((t & 31) == 0) red[t >> 5] = sm;
    __syncthreads();
    float tot = 0.0f;
#pragma unroll
    for (int i = 0; i < 8; i++) tot += red[i];
    float inv = 1.0f / tot;

    v0.x *= inv; v0.y *= inv; v0.z *= inv; v0.w *= inv;
    v1.x *= inv; v1.y *= inv; v1.z *= inv; v1.w *= inv;
    ((float4*)p)[t]       = v0;
    ((float4*)p)[t + 256] = v1;
}

// =====================================================================
// kernel_launch
// =====================================================================
extern "C" void kernel_launch(void* const* d_in, const int* in_sizes, int n_in,
                              void* d_out, int out_size)
{
    (void)in_sizes; (void)n_in; (void)out_size;
    const float* key_in   = (const float*)d_in[0];
    const float* value_in = (const float*)d_in[1];
    const float* query_in = (const float*)d_in[2];
    const float* Wk = (const float*)d_in[3];
    const float* bk = (const float*)d_in[4];
    const float* Wv = (const float*)d_in[5];
    const float* bv = (const float*)d_in[6];
    const float* Wq = (const float*)d_in[7];
    const float* bq = (const float*)d_in[8];
    const float* Wo = (const float*)d_in[9];
    const float* bo = (const float*)d_in[10];

    float* out     = (float*)d_out;
    float* topattn = out + (size_t)MROWS * DMODEL;

    void *pq, *pk, *pv, *pctx, *pas, *pbs;
    cudaGetSymbolAddress(&pq, g_q);
    cudaGetSymbolAddress(&pk, g_k);
    cudaGetSymbolAddress(&pv, g_v);
    cudaGetSymbolAddress(&pctx, g_ctx);
    cudaGetSymbolAddress(&pas, g_asplit);
    cudaGetSymbolAddress(&pbs, g_bsplit);
    __nv_bfloat16* asplit = (__nv_bfloat16*)pas;
    __nv_bfloat16* bsplit = (__nv_bfloat16*)pbs;

    cudaFuncSetAttribute(gemm_mma_kernel,
                         cudaFuncAttributeMaxDynamicSharedMemorySize, GEMM_SMEM);
    cudaFuncSetAttribute(flash_kernel,
                         cudaFuncAttributeMaxDynamicSharedMemorySize, FLASH_SMEM);

    const dim3 sgrid(MROWS * DMODEL / 4 / 256);     // split_a over 8192x1024
    const dim3 wgrid(32, 32);
    const dim3 wblk(32, 8);
    const dim3 ggrid(DMODEL / 128, MROWS / 128);    // (8, 64): N fast -> A reuse in L2

    // Q projection (scale folds in 1/sqrt(DH) = 0.125)
    split_b_kernel<<<wgrid, wblk>>>(Wq, bsplit);
    split_a_kernel<<<sgrid, 256>>>(query_in, asplit);
    gemm_mma_kernel<<<ggrid, 256, GEMM_SMEM>>>(asplit, bsplit, bq, (float*)pq, 0.125f, 1);

    // K projection
    split_b_kernel<<<wgrid, wblk>>>(Wk, bsplit);
    split_a_kernel<<<sgrid, 256>>>(key_in, asplit);
    gemm_mma_kernel<<<ggrid, 256, GEMM_SMEM>>>(asplit, bsplit, bk, (float*)pk, 1.0f, 1);

    // V projection
    split_b_kernel<<<wgrid, wblk>>>(Wv, bsplit);
    split_a_kernel<<<sgrid, 256>>>(value_in, asplit);
    gemm_mma_kernel<<<ggrid, 256, GEMM_SMEM>>>(asplit, bsplit, bv, (float*)pv, 1.0f, 1);

    // attention
    flash_kernel<<<dim3(SEQ / 128, NBH), 256, FLASH_SMEM>>>(topattn);
    softmax_rows_kernel<<<BATCH * SEQ, 256>>>(topattn);

    // output projection
    split_b_kernel<<<wgrid, wblk>>>(Wo, bsplit);
    split_a_kernel<<<sgrid, 256>>>((const float*)pctx, asplit);
    gemm_mma_kernel<<<ggrid, 256, GEMM_SMEM>>>(asplit, bsplit, bo, out, 1.0f, 0);
}

// round 17
// speedup vs baseline: 1.3138x; 1.0007x over previous
#include <cuda_runtime.h>
#include <cuda_bf16.h>
#include <math.h>
#include <stdint.h>

#define BATCH  4
#define SEQ    2048
#define DMODEL 1024
#define NHEAD  16
#define DHEAD  64
#define NBH    (BATCH * NHEAD)          // 64
#define MROWS  (BATCH * SEQ)            // 8192
#define KSPLIT 3072                     // 3 * DMODEL (bf16-split interleave)

// ---------------- scratch (no allocations allowed) ----------------
__device__ float g_q[(size_t)NBH * SEQ * DHEAD];
__device__ float g_k[(size_t)NBH * SEQ * DHEAD];
__device__ float g_v[(size_t)NBH * SEQ * DHEAD];
__device__ float g_ctx[(size_t)MROWS * DMODEL];
__device__ __nv_bfloat16 g_asplit[(size_t)MROWS * KSPLIT];   // 48 MB
__device__ __nv_bfloat16 g_bsplit[(size_t)DMODEL * KSPLIT];  // 6 MB

// =====================================================================
// Portable PTX helpers (sm_80+ features only — NO tcgen05 on this toolchain)
// =====================================================================
__device__ __forceinline__ uint32_t smem_u32(const void* p) {
    return (uint32_t)__cvta_generic_to_shared(p);
}
__device__ __forceinline__ void cp16(uint32_t dst, const void* src) {
    asm volatile("cp.async.cg.shared.global [%0], [%1], 16;" :: "r"(dst), "l"(src));
}
#define CP_COMMIT() asm volatile("cp.async.commit_group;" ::: "memory")
#define CP_WAIT1()  asm volatile("cp.async.wait_group 1;" ::: "memory")
#define CP_WAIT0()  asm volatile("cp.async.wait_group 0;" ::: "memory")

__device__ __forceinline__ void ldsm4(uint32_t* r, uint32_t addr) {
    asm volatile("ldmatrix.sync.aligned.m8n8.x4.shared.b16 {%0,%1,%2,%3}, [%4];"
                 : "=r"(r[0]), "=r"(r[1]), "=r"(r[2]), "=r"(r[3]) : "r"(addr));
}
__device__ __forceinline__ void mma16816(float* c, const uint32_t* a, const uint32_t* b) {
    asm volatile(
        "mma.sync.aligned.m16n8k16.row.col.f32.bf16.bf16.f32 "
        "{%0,%1,%2,%3}, {%4,%5,%6,%7}, {%8,%9}, {%0,%1,%2,%3};"
        : "+f"(c[0]), "+f"(c[1]), "+f"(c[2]), "+f"(c[3])
        : "r"(a[0]), "r"(a[1]), "r"(a[2]), "r"(a[3]), "r"(b[0]), "r"(b[1]));
}

// =====================================================================
// Split kernels: fp32 -> bf16 (hi,lo) in K-interleaved layout
// A:  [hi | hi | lo]      B(transposed): [hi | lo | hi]
// =====================================================================
__global__ __launch_bounds__(256) void split_a_kernel(
    const float* __restrict__ X, __nv_bfloat16* __restrict__ out)
{
    int gid = blockIdx.x * 256 + threadIdx.x;     // one float4 per thread
    float4 x = *(const float4*)(X + (size_t)gid * 4);
    int r = gid >> 8;                             // 256 float4 per row of 1024
    int c = (gid & 255) * 4;

    __nv_bfloat16 h0 = __float2bfloat16(x.x), h1 = __float2bfloat16(x.y);
    __nv_bfloat16 h2 = __float2bfloat16(x.z), h3 = __float2bfloat16(x.w);
    __nv_bfloat16 l0 = __float2bfloat16(x.x - __bfloat162float(h0));
    __nv_bfloat16 l1 = __float2bfloat16(x.y - __bfloat162float(h1));
    __nv_bfloat16 l2 = __float2bfloat16(x.z - __bfloat162float(h2));
    __nv_bfloat16 l3 = __float2bfloat16(x.w - __bfloat162float(h3));

    __nv_bfloat16 hi[4] = {h0, h1, h2, h3};
    __nv_bfloat16 lo[4] = {l0, l1, l2, l3};
    __nv_bfloat16* rp = out + (size_t)r * KSPLIT;
    *(uint2*)&rp[c]        = *(uint2*)hi;
    *(uint2*)&rp[1024 + c] = *(uint2*)hi;
    *(uint2*)&rp[2048 + c] = *(uint2*)lo;
}

// W[k][n] -> out[n][k'] : transpose + split. grid (32, 32), block (32, 8)
__global__ void split_b_kernel(const float* __restrict__ W,
                               __nv_bfloat16* __restrict__ out)
{
    __shared__ float tile[32][33];
    int n0 = blockIdx.x * 32, k0 = blockIdx.y * 32;
    int tx = threadIdx.x, ty = threadIdx.y;
#pragma unroll
    for (int i = 0; i < 32; i += 8)
        tile[ty + i][tx] = W[(size_t)(k0 + ty + i) * DMODEL + n0 + tx];
    __syncthreads();
#pragma unroll
    for (int i = 0; i < 32; i += 8) {
        int n = n0 + ty + i, k = k0 + tx;
        float x = tile[tx][ty + i];
        __nv_bfloat16 hi = __float2bfloat16(x);
        __nv_bfloat16 lo = __float2bfloat16(x - __bfloat162float(hi));
        __nv_bfloat16* rp = out + (size_t)n * KSPLIT;
        rp[k]        = hi;
        rp[1024 + k] = lo;
        rp[2048 + k] = hi;
    }
}

// =====================================================================
// mma.sync bf16 GEMM: C[8192,1024] = Asplit[8192,3072] @ Bsplit[1024,3072]^T
// CTA 128x128, 8 warps (2M x 4N), warp tile 64x32, K-stage 64, cp.async
// double buffer. smem rows padded to 144B (9 chunks) -> conflict-free ldmatrix.
// grid (N/128 = 8, M/128 = 64)  (x-fast -> A tile reused via L2)
// =====================================================================
#define BK        64
#define ROWB      144                     // padded row stride in bytes
#define TILEB     (128 * ROWB)            // 18432 B per matrix per stage
#define GEMM_SMEM (4 * TILEB)             // 73728 B  (A0 B0 A1 B1)
#define NSTAGE    (KSPLIT / BK)           // 48

__device__ __forceinline__ void gemm_load_stage(
    uint32_t sa, uint32_t sb, const __nv_bfloat16* __restrict__ A,
    const __nv_bfloat16* __restrict__ B, int row0, int col0, int k0, int tid)
{
#pragma unroll
    for (int t = 0; t < 8; t++) {
        int idx = tid + t * 256;              // 0..2047
        int row = (idx >> 3) & 127;
        int c   = idx & 7;                    // 16B chunk
        const __nv_bfloat16* src = (idx < 1024)
            ? A + (size_t)(row0 + row) * KSPLIT + k0 + c * 8
            : B + (size_t)(col0 + row) * KSPLIT + k0 + c * 8;
        uint32_t dst = ((idx < 1024) ? sa : sb) + row * ROWB + c * 16;
        cp16(dst, src);
    }
}

__global__ __launch_bounds__(256) void gemm_mma_kernel(
    const __nv_bfloat16* __restrict__ A, const __nv_bfloat16* __restrict__ B,
    const float* __restrict__ bias, float* __restrict__ out,
    float scale, int head_split)
{
    extern __shared__ char smem[];
    const uint32_t sb0 = smem_u32(smem);
    const int tid  = threadIdx.x;
    const int wid  = tid >> 5;
    const int lane = tid & 31;
    const int wy   = wid >> 2;            // 0..1  (M)
    const int wx   = wid & 3;             // 0..3  (N)
    const int col0 = blockIdx.x * 128;
    const int row0 = blockIdx.y * 128;

    // stage smem bases: A0 B0 A1 B1
    const uint32_t sa[2] = {sb0,             sb0 + 2 * TILEB};
    const uint32_t sbv[2] = {sb0 + TILEB,    sb0 + 3 * TILEB};

    // per-thread ldmatrix base addresses (within a stage buffer)
    // A: lanes 0-15 -> rows (wy*64 + lane), chunk 0 ; lanes 16-31 -> same rows, chunk 1
    const uint32_t a_off = (uint32_t)((wy * 64 + (lane & 15)) * ROWB + (lane >> 4) * 16);
    // B: rows = wx*32 + ((lane>>4)&1)*8 + (lane&7), chunk = (lane>>3)&1
    const uint32_t b_off = (uint32_t)((wx * 32 + ((lane >> 4) & 1) * 8 + (lane & 7)) * ROWB
                                      + ((lane >> 3) & 1) * 16);

    float acc[4][4][4];
#pragma unroll
    for (int i = 0; i < 4; i++)
#pragma unroll
        for (int j = 0; j < 4; j++)
#pragma unroll
            for (int e = 0; e < 4; e++) acc[i][j][e] = 0.0f;

    gemm_load_stage(sa[0], sbv[0], A, B, row0, col0, 0, tid);
    CP_COMMIT();

    for (int s = 0; s < NSTAGE; s++) {
        const int buf = s & 1;
        if (s + 1 < NSTAGE) {
            gemm_load_stage(sa[buf ^ 1], sbv[buf ^ 1], A, B, row0, col0,
                            (s + 1) * BK, tid);
            CP_COMMIT();
            CP_WAIT1();
        } else {
            CP_WAIT0();
        }
        __syncthreads();

        const uint32_t abase = sa[buf] + a_off;
        const uint32_t bbase = sbv[buf] + b_off;
#pragma unroll
        for (int kk = 0; kk < BK / 16; kk++) {
            uint32_t af[4][4], bf[8];
#pragma unroll
            for (int i = 0; i < 4; i++)
                ldsm4(af[i], abase + i * 16 * ROWB + kk * 32);
#pragma unroll
            for (int j2 = 0; j2 < 2; j2++)
                ldsm4(&bf[j2 * 4], bbase + j2 * 16 * ROWB + kk * 32);
#pragma unroll
            for (int i = 0; i < 4; i++)
#pragma unroll
                for (int j = 0; j < 4; j++)
                    mma16816(acc[i][j], af[i], &bf[j * 2]);
        }
        __syncthreads();
    }

    // ---- epilogue: bias + scale + (optional) head-split store ----
#pragma unroll
    for (int i = 0; i < 4; i++) {
        const int r0t = row0 + wy * 64 + i * 16 + (lane >> 2);
#pragma unroll
        for (int j = 0; j < 4; j++) {
            const int cc = col0 + wx * 32 + j * 8 + (lane & 3) * 2;
            float2 bi = *(const float2*)&bias[cc];
            float2 v0, v1;
            v0.x = (acc[i][j][0] + bi.x) * scale;
            v0.y = (acc[i][j][1] + bi.y) * scale;
            v1.x = (acc[i][j][2] + bi.x) * scale;
            v1.y = (acc[i][j][3] + bi.y) * scale;
            if (head_split) {
                const int h = cc >> 6, d = cc & 63;
                int bb = r0t >> 11, ss = r0t & (SEQ - 1);
                *(float2*)&out[((size_t)(bb * NHEAD + h) * SEQ + ss) * DHEAD + d] = v0;
                int r1t = r0t + 8;
                bb = r1t >> 11; ss = r1t & (SEQ - 1);
                *(float2*)&out[((size_t)(bb * NHEAD + h) * SEQ + ss) * DHEAD + d] = v1;
            } else {
                *(float2*)&out[(size_t)r0t * DMODEL + cc]       = v0;
                *(float2*)&out[(size_t)(r0t + 8) * DMODEL + cc] = v1;
            }
        }
    }
}

// =====================================================================
// Flash attention, fp32 (unchanged).  grid = (S/128, BH), block 256.
// =====================================================================
#define QSTRIDE 68
#define PSTRIDE 132
#define FLASH_SMEM ((3 * 128 * QSTRIDE + 128 * PSTRIDE) * 4)   // 172032 B

__global__ __launch_bounds__(256, 1) void flash_kernel(float* __restrict__ topattn)
{
    extern __shared__ float fsm[];
    float* Qs = fsm;
    float* Ks = fsm + 128 * QSTRIDE;
    float* Vs = fsm + 2 * 128 * QSTRIDE;
    float* Ps = fsm + 3 * 128 * QSTRIDE;

    const int tid = threadIdx.x;
    const int tx  = tid & 15;
    const int ty  = tid >> 4;
    const int bh  = blockIdx.y;
    const int q0  = blockIdx.x * 128;
    const int b   = bh >> 4;
    const int h   = bh & 15;

    const float* Qg = g_q + (size_t)bh * SEQ * DHEAD + (size_t)q0 * DHEAD;
    const float* Kg = g_k + (size_t)bh * SEQ * DHEAD;
    const float* Vg = g_v + (size_t)bh * SEQ * DHEAD;

#pragma unroll
    for (int t = 0; t < 8; t++) {
        int idx = tid + t * 256;
        int row = idx >> 4;
        int c4  = (idx & 15) << 2;
        *(float4*)&Qs[row * QSTRIDE + c4] = *(const float4*)(Qg + row * DHEAD + c4);
    }

    int rloc[8];
#pragma unroll
    for (int i = 0; i < 8; i++)
        rloc[i] = (i < 4) ? (ty * 4 + i) : (64 + ty * 4 + i - 4);

    float mrow[8], lrow[8], ctx[8][4];
#pragma unroll
    for (int i = 0; i < 8; i++) {
        mrow[i] = -3.0e38f;
        lrow[i] = 0.0f;
#pragma unroll
        for (int j = 0; j < 4; j++) ctx[i][j] = 0.0f;
    }

    for (int kt = 0; kt < SEQ / 128; kt++) {
        const int k0 = kt * 128;
        __syncthreads();
#pragma unroll
        for (int t = 0; t < 8; t++) {
            int idx = tid + t * 256;
            int row = idx >> 4;
            int c4  = (idx & 15) << 2;
            *(float4*)&Ks[row * QSTRIDE + c4] = *(const float4*)(Kg + (k0 + row) * DHEAD + c4);
            *(float4*)&Vs[row * QSTRIDE + c4] = *(const float4*)(Vg + (k0 + row) * DHEAD + c4);
        }
        __syncthreads();

        float s[8][8];
#pragma unroll
        for (int i = 0; i < 8; i++)
#pragma unroll
            for (int j = 0; j < 8; j++) s[i][j] = 0.0f;

#pragma unroll 2
        for (int d = 0; d < DHEAD; d += 4) {
            float4 a4[8], b4[8];
#pragma unroll
            for (int i = 0; i < 8; i++)
                a4[i] = *(const float4*)&Qs[rloc[i] * QSTRIDE + d];
#pragma unroll
            for (int j = 0; j < 8; j++) {
                int col = (j < 4) ? (tx * 4 + j) : (64 + tx * 4 + j - 4);
                b4[j] = *(const float4*)&Ks[col * QSTRIDE + d];
            }
#pragma unroll
            for (int i = 0; i < 8; i++)
#pragma unroll
                for (int j = 0; j < 8; j++) {
                    s[i][j] = fmaf(a4[i].x, b4[j].x, s[i][j]);
                    s[i][j] = fmaf(a4[i].y, b4[j].y, s[i][j]);
                    s[i][j] = fmaf(a4[i].z, b4[j].z, s[i][j]);
                    s[i][j] = fmaf(a4[i].w, b4[j].w, s[i][j]);
                }
        }

        if (h == 0) {
            float* op = topattn + ((size_t)b * SEQ + q0) * SEQ + k0;
#pragma unroll
            for (int i = 0; i < 8; i++) {
                float* rp = op + (size_t)rloc[i] * SEQ;
                *(float4*)&rp[tx * 4]      = make_float4(s[i][0], s[i][1], s[i][2], s[i][3]);
                *(float4*)&rp[64 + tx * 4] = make_float4(s[i][4], s[i][5], s[i][6], s[i][7]);
            }
        }

#pragma unroll
        for (int i = 0; i < 8; i++) {
            float mx = s[i][0];
#pragma unroll
            for (int j = 1; j < 8; j++) mx = fmaxf(mx, s[i][j]);
#pragma unroll
            for (int o = 8; o >= 1; o >>= 1)
                mx = fmaxf(mx, __shfl_xor_sync(0xffffffffu, mx, o, 16));
            float mn    = fmaxf(mrow[i], mx);
            float alpha = __expf(mrow[i] - mn);
            mrow[i] = mn;
            lrow[i] *= alpha;
#pragma unroll
            for (int j = 0; j < 4; j++) ctx[i][j] *= alpha;
            float rs = 0.0f;
#pragma unroll
            for (int j = 0; j < 8; j++) {
                float p = __expf(s[i][j] - mn);
                s[i][j] = p;
                rs += p;
            }
#pragma unroll
            for (int o = 8; o >= 1; o >>= 1)
                rs += __shfl_xor_sync(0xffffffffu, rs, o, 16);
            lrow[i] += rs;
        }

#pragma unroll
        for (int i = 0; i < 8; i++) {
            float* pp = &Ps[rloc[i] * PSTRIDE];
            *(float4*)&pp[tx * 4]      = make_float4(s[i][0], s[i][1], s[i][2], s[i][3]);
            *(float4*)&pp[64 + tx * 4] = make_float4(s[i][4], s[i][5], s[i][6], s[i][7]);
        }
        __syncthreads();

#pragma unroll 2
        for (int kc = 0; kc < 128; kc += 4) {
            float4 v4[4];
#pragma unroll
            for (int kk = 0; kk < 4; kk++)
                v4[kk] = *(const float4*)&Vs[(kc + kk) * QSTRIDE + tx * 4];
#pragma unroll
            for (int i = 0; i < 8; i++) {
                float4 p4 = *(const float4*)&Ps[rloc[i] * PSTRIDE + kc];
                ctx[i][0] = fmaf(p4.x, v4[0].x, ctx[i][0]);
                ctx[i][0] = fmaf(p4.y, v4[1].x, ctx[i][0]);
                ctx[i][0] = fmaf(p4.z, v4[2].x, ctx[i][0]);
                ctx[i][0] = fmaf(p4.w, v4[3].x, ctx[i][0]);
                ctx[i][1] = fmaf(p4.x, v4[0].y, ctx[i][1]);
                ctx[i][1] = fmaf(p4.y, v4[1].y, ctx[i][1]);
                ctx[i][1] = fmaf(p4.z, v4[2].y, ctx[i][1]);
                ctx[i][1] = fmaf(p4.w, v4[3].y, ctx[i][1]);
                ctx[i][2] = fmaf(p4.x, v4[0].z, ctx[i][2]);
                ctx[i][2] = fmaf(p4.y, v4[1].z, ctx[i][2]);
                ctx[i][2] = fmaf(p4.z, v4[2].z, ctx[i][2]);
                ctx[i][2] = fmaf(p4.w, v4[3].z, ctx[i][2]);
                ctx[i][3] = fmaf(p4.x, v4[0].w, ctx[i][3]);
                ctx[i][3] = fmaf(p4.y, v4[1].w, ctx[i][3]);
                ctx[i][3] = fmaf(p4.z, v4[2].w, ctx[i][3]);
                ctx[i][3] = fmaf(p4.w, v4[3].w, ctx[i][3]);
            }
        }
    }

#pragma unroll
    for (int i = 0; i < 8; i++) {
        float inv = 1.0f / lrow[i];
        int   r   = q0 + rloc[i];
        size_t idx = ((size_t)b * SEQ + r) * DMODEL + h * DHEAD + tx * 4;
        *(float4*)&g_ctx[idx] =
            make_float4(ctx[i][0] * inv, ctx[i][1] * inv, ctx[i][2] * inv, ctx[i][3] * inv);
    }
}

// =====================================================================
// In-place row softmax over top_attn (rows of 2048). grid = B*S.
// =====================================================================
__global__ __launch_bounds__(256) void softmax_rows_kernel(float* __restrict__ data)
{
    __shared__ float red[8];
    float* p = data + (size_t)blockIdx.x * SEQ;
    const int t = threadIdx.x;

    float4 v0 = ((const float4*)p)[t];
    float4 v1 = ((const float4*)p)[t + 256];

    float mx = fmaxf(fmaxf(fmaxf(v0.x, v0.y), fmaxf(v0.z, v0.w)),
                     fmaxf(fmaxf(v1.x, v1.y), fmaxf(v1.z, v1.w)));
#pragma unroll
    for (int o = 16; o >= 1; o >>= 1)
        mx = fmaxf(mx, __shfl_xor_sync(0xffffffffu, mx, o));
    if ((t & 31) == 0) red[t >> 5] = mx;
    __syncthreads();
    float m = red[0];
#pragma unroll
    for (int i = 1; i < 8; i++) m = fmaxf(m, red[i]);
    __syncthreads();

    v0.x = __expf(v0.x - m); v0.y = __expf(v0.y - m);
    v0.z = __expf(v0.z - m); v0.w = __expf(v0.w - m);
    v1.x = __expf(v1.x - m); v1.y = __expf(v1.y - m);
    v1.z = __expf(v1.z - m); v1.w = __expf(v1.w - m);

    float sm = v0.x + v0.y + v0.z + v0.w + v1.x + v1.y + v1.z + v1.w;
#pragma unroll
    for (int o = 16; o >= 1; o >>= 1)
        sm += __shfl_xor_sync(0xffffffffu, sm, o);
    if ((t & 31) == 0) red[t >> 5] = sm;
    __syncthreads();
    float tot = 0.0f;
#pragma unroll
    for (int i = 0; i < 8; i++) tot += red[i];
    float inv = 1.0f / tot;

    v0.x *= inv; v0.y *= inv; v0.z *= inv; v0.w *= inv;
    v1.x *= inv; v1.y *= inv; v1.z *= inv; v1.w *= inv;
    ((float4*)p)[t]       = v0;
    ((float4*)p)[t + 256] = v1;
}

// =====================================================================
// kernel_launch
// =====================================================================
extern "C" void kernel_launch(void* const* d_in, const int* in_sizes, int n_in,
                              void* d_out, int out_size)
{
    (void)in_sizes; (void)n_in; (void)out_size;
    const float* key_in   = (const float*)d_in[0];
    const float* value_in = (const float*)d_in[1];
    const float* query_in = (const float*)d_in[2];
    const float* Wk = (const float*)d_in[3];
    const float* bk = (const float*)d_in[4];
    const float* Wv = (const float*)d_in[5];
    const float* bv = (const float*)d_in[6];
    const float* Wq = (const float*)d_in[7];
    const float* bq = (const float*)d_in[8];
    const float* Wo = (const float*)d_in[9];
    const float* bo = (const float*)d_in[10];

    float* out     = (float*)d_out;
    float* topattn = out + (size_t)MROWS * DMODEL;

    void *pq, *pk, *pv, *pctx, *pas, *pbs;
    cudaGetSymbolAddress(&pq, g_q);
    cudaGetSymbolAddress(&pk, g_k);
    cudaGetSymbolAddress(&pv, g_v);
    cudaGetSymbolAddress(&pctx, g_ctx);
    cudaGetSymbolAddress(&pas, g_asplit);
    cudaGetSymbolAddress(&pbs, g_bsplit);
    __nv_bfloat16* asplit = (__nv_bfloat16*)pas;
    __nv_bfloat16* bsplit = (__nv_bfloat16*)pbs;

    cudaFuncSetAttribute(gemm_mma_kernel,
                         cudaFuncAttributeMaxDynamicSharedMemorySize, GEMM_SMEM);
    cudaFuncSetAttribute(flash_kernel,
                         cudaFuncAttributeMaxDynamicSharedMemorySize, FLASH_SMEM);

    const dim3 sgrid(MROWS * DMODEL / 4 / 256);     // split_a over 8192x1024
    const dim3 wgrid(32, 32);
    const dim3 wblk(32, 8);
    const dim3 ggrid(DMODEL / 128, MROWS / 128);    // (8, 64): N fast -> A reuse in L2

    // Q projection (scale folds in 1/sqrt(DH) = 0.125)
    split_b_kernel<<<wgrid, wblk>>>(Wq, bsplit);
    split_a_kernel<<<sgrid, 256>>>(query_in, asplit);
    gemm_mma_kernel<<<ggrid, 256, GEMM_SMEM>>>(asplit, bsplit, bq, (float*)pq, 0.125f, 1);

    // K projection
    split_b_kernel<<<wgrid, wblk>>>(Wk, bsplit);
    split_a_kernel<<<sgrid, 256>>>(key_in, asplit);
    gemm_mma_kernel<<<ggrid, 256, GEMM_SMEM>>>(asplit, bsplit, bk, (float*)pk, 1.0f, 1);

    // V projection
    split_b_kernel<<<wgrid, wblk>>>(Wv, bsplit);
    split_a_kernel<<<sgrid, 256>>>(value_in, asplit);
    gemm_mma_kernel<<<ggrid, 256, GEMM_SMEM>>>(asplit, bsplit, bv, (float*)pv, 1.0f, 1);

    // attention
    flash_kernel<<<dim3(SEQ / 128, NBH), 256, FLASH_SMEM>>>(topattn);
    softmax_rows_kernel<<<BATCH * SEQ, 256>>>(topattn);

    // output projection
    split_b_kernel<<<wgrid, wblk>>>(Wo, bsplit);
    split_a_kernel<<<sgrid, 256>>>((const float*)pctx, asplit);
    gemm_mma_kernel<<<ggrid, 256, GEMM_SMEM>>>(asplit, bsplit, bo, out, 1.0f, 0);
}